// round 15
// baseline (speedup 1.0000x reference)
#include <cuda_runtime.h>
#include <cuda_bf16.h>
#include <cstdint>

#define EPSF 1e-5f

// Problem dims
#define NN  64
#define CC  64
#define TD  300
#define VV  25
#define SS  3
#define ICn 16
#define OCn 64
#define NCOL (TD*VV)          // 7500

// kConvM tiling
#define TCB   20
#define MCH   (TD/TCB)        // 15 chunks (also M split-k partials)
#define COLSB (TCB*VV)        // 500

// kB tiling
#define CT    64                      // cols per block
#define NTBL  ((NCOL + CT - 1)/CT)    // 118
#define XMS   68                      // xm row stride
#define WST   68                      // W row stride ([o][k], LDSM conflict-free)

typedef unsigned long long u64;

__device__ float g_Mpart[MCH*NN*SS*VV*VV];
__device__ float g_Afrag[(size_t)NN*96*32];  // A_adp in mma frag layout, tf32
__device__ float g_wdT  [SS*OCn*CC];         // [s][o][c], BN-scaled, tf32 bits
__device__ float g_off  [OCn];

__device__ __forceinline__ float tanh_fast(float x) {
    float y;
    asm("tanh.approx.f32 %0, %1;" : "=f"(y) : "f"(x));
    return y;
}
__device__ __forceinline__ uint32_t f2tf32(float x) {
    uint32_t u;
    asm("cvt.rna.tf32.f32 %0, %1;" : "=r"(u) : "f"(x));
    return u;
}
__device__ __forceinline__ uint32_t prmt(uint32_t a, uint32_t b, uint32_t sel) {
    uint32_t d;
    asm("prmt.b32 %0, %1, %2, %3;" : "=r"(d) : "r"(a), "r"(b), "r"(sel));
    return d;
}
__device__ __forceinline__ uint32_t bfpack(float lo, float hi) {
    __nv_bfloat162 h = __floats2bfloat162_rn(lo, hi);
    return *reinterpret_cast<uint32_t*>(&h);
}
__device__ __forceinline__ void mma_tf32(float d[4],
    uint32_t a0, uint32_t a1, uint32_t a2, uint32_t a3,
    uint32_t b0, uint32_t b1)
{
    asm volatile(
        "mma.sync.aligned.m16n8k8.row.col.f32.tf32.tf32.f32 "
        "{%0,%1,%2,%3}, {%4,%5,%6,%7}, {%8,%9}, {%0,%1,%2,%3};\n"
        : "+f"(d[0]), "+f"(d[1]), "+f"(d[2]), "+f"(d[3])
        : "r"(a0), "r"(a1), "r"(a2), "r"(a3), "r"(b0), "r"(b1));
}
__device__ __forceinline__ void mma_bf16(float d[4],
    uint32_t a0, uint32_t a1, uint32_t a2, uint32_t a3,
    uint32_t b0, uint32_t b1)
{
    asm volatile(
        "mma.sync.aligned.m16n8k16.row.col.f32.bf16.bf16.f32 "
        "{%0,%1,%2,%3}, {%4,%5,%6,%7}, {%8,%9}, {%0,%1,%2,%3};\n"
        : "+f"(d[0]), "+f"(d[1]), "+f"(d[2]), "+f"(d[3])
        : "r"(a0), "r"(a1), "r"(a2), "r"(a3), "r"(b0), "r"(b1));
}
__device__ __forceinline__ void ldsm4(uint32_t r[4], uint32_t addr)
{
    asm volatile(
        "ldmatrix.sync.aligned.m8n8.x4.shared.b16 {%0,%1,%2,%3}, [%4];"
        : "=r"(r[0]), "=r"(r[1]), "=r"(r[2]), "=r"(r[3]) : "r"(addr));
}

// ---------------------------------------------------------------------------
// kConvM: per (chunk of 20 t, s, n):
//  Phase 1 (tf32 mma): conv + tanh -> bf16 mma fragments in smem.
//  Phase 2 (bf16 mma): partial M over 20 k16-steps; reduction; g_Mpart.
// ---------------------------------------------------------------------------
__global__ __launch_bounds__(256, 2) void kConvM(
    const float* __restrict__ x,
    const float* __restrict__ wa, const float* __restrict__ ba,
    const float* __restrict__ wb, const float* __restrict__ bb,
    const float* __restrict__ gag, const float* __restrict__ gab,
    const float* __restrict__ gam, const float* __restrict__ gav,
    const float* __restrict__ gbg, const float* __restrict__ gbb,
    const float* __restrict__ gbm, const float* __restrict__ gbv)
{
    __shared__ __align__(16) uint32_t s_fr[2*TCB*256];
    __shared__ float s_sh[32];

    uint32_t* s_aF = s_fr;
    uint32_t* s_bF = s_fr + TCB*256;
    float*    s_wf = reinterpret_cast<float*>(s_fr);

    const int tid  = threadIdx.x;
    const int wid  = tid >> 5;
    const int lane = tid & 31;
    const int gr   = lane >> 2;
    const int tc   = lane & 3;
    const int chunk = blockIdx.x;
    const int s     = blockIdx.y;
    const int n     = blockIdx.z;

    for (int idx = tid; idx < 32*CC; idx += 256) {
        int io = idx >> 6, c = idx & 63;
        int i  = io & 15;
        bool isB = io >= 16;
        float g  = isB ? gbg[s*ICn+i] : gag[s*ICn+i];
        float vv = isB ? gbv[s*ICn+i] : gav[s*ICn+i];
        float wv = isB ? wb[s*ICn*CC + i*CC + c] : wa[s*ICn*CC + i*CC + c];
        float sc = g * rsqrtf(vv + EPSF);
        s_wf[io*68 + c] = __uint_as_float(f2tf32(wv * sc));
    }
    if (tid < 32) {
        int i = tid & 15;
        bool isB = tid >= 16;
        float g  = isB ? gbg[s*ICn+i] : gag[s*ICn+i];
        float vv = isB ? gbv[s*ICn+i] : gav[s*ICn+i];
        float bs = isB ? bb[s*ICn+i]  : ba[s*ICn+i];
        float mn = isB ? gbm[s*ICn+i] : gam[s*ICn+i];
        float bt = isB ? gbb[s*ICn+i] : gab[s*ICn+i];
        float sc = g * rsqrtf(vv + EPSF);
        s_sh[tid] = (bs - mn) * sc + bt;
    }
    __syncthreads();

    const uint32_t* wfu = reinterpret_cast<const uint32_t*>(s_wf);
    uint32_t af[2][8][4];
    #pragma unroll
    for (int mi = 0; mi < 2; mi++)
        #pragma unroll
        for (int kt = 0; kt < 8; kt++) {
            int r0 = (mi*16 + gr)*68 + kt*8 + tc;
            af[mi][kt][0] = wfu[r0];
            af[mi][kt][1] = wfu[r0 + 8*68];
            af[mi][kt][2] = wfu[r0 + 4];
            af[mi][kt][3] = wfu[r0 + 8*68 + 4];
        }
    const float sha0 = s_sh[gr],      sha8 = s_sh[gr + 8];
    const float shb0 = s_sh[16 + gr], shb8 = s_sh[24 + gr];
    __syncthreads();

    for (int idx = tid; idx < 2*TCB*256; idx += 256) s_fr[idx] = 0u;
    __syncthreads();

    const float* xn = x + (size_t)n*(CC*NCOL);
    const int lwbase = wid*64;
    const int tck = gr >> 1;
    const bool evenGr = ((gr & 1) == 0);

    #pragma unroll 2
    for (int nt = 0; nt < 8; nt++) {
        const int n0 = nt*8;
        const int lcol = lwbase + n0 + gr;
        const bool ld  = (lcol < COLSB);
        const int colg = chunk*COLSB + lcol;

        uint32_t bf[8][2];
        const float* xp = xn + colg;
        #pragma unroll
        for (int kt = 0; kt < 8; kt++) {
            float v0 = ld ? xp[(size_t)(kt*8 + tc)*NCOL]     : 0.f;
            float v1 = ld ? xp[(size_t)(kt*8 + tc + 4)*NCOL] : 0.f;
            bf[kt][0] = f2tf32(v0);
            bf[kt][1] = f2tf32(v1);
        }

        float da[4] = {0.f, 0.f, 0.f, 0.f};
        float dbv[4] = {0.f, 0.f, 0.f, 0.f};
        #pragma unroll
        for (int kt = 0; kt < 8; kt++) {
            mma_tf32(da,  af[0][kt][0], af[0][kt][1], af[0][kt][2], af[0][kt][3],
                     bf[kt][0], bf[kt][1]);
            mma_tf32(dbv, af[1][kt][0], af[1][kt][1], af[1][kt][2], af[1][kt][3],
                     bf[kt][0], bf[kt][1]);
        }

        uint32_t ha  = bfpack(tanh_fast(da[0]  + sha0), tanh_fast(da[1]  + sha0));
        uint32_t ha8 = bfpack(tanh_fast(da[2]  + sha8), tanh_fast(da[3]  + sha8));
        uint32_t hb  = bfpack(tanh_fast(dbv[0] + shb0), tanh_fast(dbv[1] + shb0));
        uint32_t hb8 = bfpack(tanh_fast(dbv[2] + shb8), tanh_fast(dbv[3] + shb8));

        uint32_t pa  = __shfl_xor_sync(0xffffffffu, ha,  4);
        uint32_t pa8 = __shfl_xor_sync(0xffffffffu, ha8, 4);
        uint32_t pb  = __shfl_xor_sync(0xffffffffu, hb,  4);
        uint32_t pb8 = __shfl_xor_sync(0xffffffffu, hb8, 4);

        const int lc0 = lwbase + n0 + 2*tc;

        if (evenGr) {
            uint32_t wlo0 = prmt(ha,  pa,  0x5410);
            uint32_t whi0 = prmt(ha8, pa8, 0x5410);
            uint32_t wlo1 = prmt(ha,  pa,  0x7632);
            uint32_t whi1 = prmt(ha8, pa8, 0x7632);
            #pragma unroll
            for (int cc2 = 0; cc2 < 2; cc2++) {
                int lc = lc0 + cc2;
                if (lc < COLSB) {
                    int tl = lc / 25, v = lc - 25*tl;
                    int mt = v >> 4, vt = v & 15;
                    int rsel = vt >> 3, grt = vt & 7;
                    uint32_t wlo = cc2 ? wlo1 : wlo0;
                    uint32_t whi = cc2 ? whi1 : whi0;
                    s_aF[tl*256 + (mt*4 + rsel    )*32 + grt*4 + tck] = wlo;
                    s_aF[tl*256 + (mt*4 + 2 + rsel)*32 + grt*4 + tck] = whi;
                }
            }
        } else {
            uint32_t wlo0 = prmt(pb,  hb,  0x5410);
            uint32_t whi0 = prmt(pb8, hb8, 0x5410);
            uint32_t wlo1 = prmt(pb,  hb,  0x7632);
            uint32_t whi1 = prmt(pb8, hb8, 0x7632);
            #pragma unroll
            for (int cc2 = 0; cc2 < 2; cc2++) {
                int lc = lc0 + cc2;
                if (lc < COLSB) {
                    int tl = lc / 25, v = lc - 25*tl;
                    int wt = v >> 3, grw = v & 7;
                    uint32_t wlo = cc2 ? wlo1 : wlo0;
                    uint32_t whi = cc2 ? whi1 : whi0;
                    s_bF[tl*256 + (wt*2    )*32 + grw*4 + tck] = wlo;
                    s_bF[tl*256 + (wt*2 + 1)*32 + grw*4 + tck] = whi;
                }
            }
        }
    }
    __syncthreads();

    float acc[2][4][4];
    #pragma unroll
    for (int mt = 0; mt < 2; mt++)
        #pragma unroll
        for (int wt = 0; wt < 4; wt++)
            #pragma unroll
            for (int r = 0; r < 4; r++) acc[mt][wt][r] = 0.f;

    for (int ls = wid; ls < TCB; ls += 8) {
        const uint32_t* pa = s_aF + ls*256 + lane;
        const uint32_t* pb = s_bF + ls*256 + lane;
        uint32_t aw[2][4], bw[4][2];
        #pragma unroll
        for (int mt = 0; mt < 2; mt++)
            #pragma unroll
            for (int r = 0; r < 4; r++)
                aw[mt][r] = pa[(mt*4 + r)*32];
        #pragma unroll
        for (int wt = 0; wt < 4; wt++)
            #pragma unroll
            for (int r = 0; r < 2; r++)
                bw[wt][r] = pb[(wt*2 + r)*32];
        #pragma unroll
        for (int mt = 0; mt < 2; mt++)
            #pragma unroll
            for (int wt = 0; wt < 4; wt++)
                mma_bf16(acc[mt][wt], aw[mt][0], aw[mt][1], aw[mt][2], aw[mt][3],
                         bw[wt][0], bw[wt][1]);
    }
    __syncthreads();

    float* s_red = reinterpret_cast<float*>(s_fr);
    float* my = s_red + wid*1024;
    #pragma unroll
    for (int mt = 0; mt < 2; mt++)
        #pragma unroll
        for (int wt = 0; wt < 4; wt++)
            #pragma unroll
            for (int r = 0; r < 4; r++)
                my[((mt*4 + wt)*4 + r)*32 + lane] = acc[mt][wt][r];
    __syncthreads();

    #pragma unroll
    for (int rep = 0; rep < 4; rep++) {
        int pos = tid + rep*256;
        float v = 0.f;
        #pragma unroll
        for (int w8 = 0; w8 < 8; w8++)
            v += s_red[w8*1024 + pos];
        int lp  = pos & 31;
        int reg = (pos >> 5) & 3;
        int wt  = (pos >> 7) & 3;
        int mt  = pos >> 9;
        int grp = lp >> 2, tcp = lp & 3;
        int vv = mt*16 + grp + (reg >> 1)*8;
        int ww = wt*8 + 2*tcp + (reg & 1);
        if (vv < VV && ww < VV)
            g_Mpart[((size_t)chunk*NN*SS + (size_t)n*SS + s)*(VV*VV)
                    + vv*VV + ww] = v;
    }
}

// ---------------------------------------------------------------------------
// kA2: reduce partials, A_adp in kB's mma fragment layout.
// ---------------------------------------------------------------------------
__global__ void kA2(const float* __restrict__ A, const float* __restrict__ alpha)
{
    int idx = blockIdx.x * 256 + threadIdx.x;
    if (idx >= NN*96*32) return;
    int lane = idx & 31;
    int r    = (idx >> 5) % 96;
    int n    = idx / (96*32);
    int reg = r & 1;
    int wt  = (r >> 1) & 3;
    int kt  = (r >> 3) & 3;
    int s   = r >> 5;
    int v = kt*8 + (lane & 3) + reg*4;
    int w = wt*8 + (lane >> 2);
    float val = 0.f;
    if (v < VV && w < VV) {
        int mi = (n*SS + s)*(VV*VV) + v*VV + w;
        float m = 0.f;
        #pragma unroll
        for (int ch = 0; ch < MCH; ch++)
            m += g_Mpart[ch*(NN*SS*VV*VV) + mi];
        val = A[s*(VV*VV) + v*VV + w]
            + tanhf(m * (1.f/(float)(ICn*TD))) * alpha[0];
    }
    g_Afrag[idx] = __uint_as_float(f2tf32(val));
}

// ---------------------------------------------------------------------------
// kW: W -> [s][o][c] (native layout), BN scale folded, tf32-rounded. g_off.
// ---------------------------------------------------------------------------
__global__ void kW(const float* __restrict__ wd, const float* __restrict__ db,
                   const float* __restrict__ bng, const float* __restrict__ bnb,
                   const float* __restrict__ bnm, const float* __restrict__ bnv)
{
    int idx = blockIdx.x * 256 + threadIdx.x;
    if (idx < SS*OCn*CC) {
        int o = (idx >> 6) & 63;
        float sc = bng[o] * rsqrtf(bnv[o] + EPSF);
        g_wdT[idx] = __uint_as_float(f2tf32(wd[idx] * sc));
    }
    if (blockIdx.x == 0 && threadIdx.x < OCn) {
        int o = threadIdx.x;
        float sc = bng[o] * rsqrtf(bnv[o] + EPSF);
        float ds = db[o] + db[OCn + o] + db[2*OCn + o];
        g_off[o] = (ds - bnm[o]) * sc + bnb[o];
    }
}

// ---------------------------------------------------------------------------
// kB: block = (64-col tile, n), 4 blocks/SM. For each s:
//   GEMM1 (mma tf32): xm[col][c]; B-frags loaded once per wt (mi inner)
//   GEMM2 (mma tf32): D[col][o] += xm @ W_s; fragments via ldmatrix.x4
// Epilogue: dY -> smem transpose -> coalesced float4 STG + residual.
// ---------------------------------------------------------------------------
__global__ __launch_bounds__(256, 4) void kB(
    const float* __restrict__ x,
    float* __restrict__ out)
{
    extern __shared__ float sm[];
    float* s_xm  = sm;                  // [64][68]  tf32 bits / epilogue s_out
    float* s_w   = s_xm + CT*XMS;       // [64][68]  tf32 bits, [o][k] per s
    float* s_Af  = s_w  + OCn*WST;      // [96][32]  A_adp frags, tf32
    float* s_off = s_Af + 96*32;        // [64]

    const int tid  = threadIdx.x;
    const int wid  = tid >> 5;
    const int lane = tid & 31;
    const int gr   = lane >> 2;
    const int tc   = lane & 3;
    const int blk  = blockIdx.x;
    const int n    = blockIdx.y;
    const int cbase = blk * CT;
    const int t0    = cbase / VV;
    const int coff  = cbase - t0*VV;

    const float* xn = x + (size_t)n*(CC*NCOL);

    // ---- prologue staging ----
    {
        const float4* ag = reinterpret_cast<const float4*>(
            g_Afrag + (size_t)n*(96*32));
        float4* as = reinterpret_cast<float4*>(s_Af);
        for (int idx = tid; idx < 96*32/4; idx += 256)
            as[idx] = ag[idx];
    }
    if (tid < OCn) s_off[tid] = g_off[tid];

    // warp roles
    const int tl = wid & 3;
    const int oh = wid >> 2;
    const int ctq = wid & 3;

    // x A-fragments in registers (s-invariant)
    uint32_t ax[2][4][4];
    {
        const int colB = (t0 + tl)*VV;
        #pragma unroll
        for (int mi = 0; mi < 2; mi++) {
            const int r0 = (oh + 2*mi)*16 + gr;
            const float* b0p = xn + (size_t)r0*NCOL;
            const float* b1p = b0p + (size_t)8*NCOL;
            #pragma unroll
            for (int kt = 0; kt < 4; kt++) {
                int c0i = colB + kt*8 + tc;
                int c1i = c0i + 4;
                bool k0 = (c0i < NCOL);
                bool k1 = (c1i < NCOL);
                ax[mi][kt][0] = f2tf32(k0 ? b0p[c0i] : 0.f);
                ax[mi][kt][1] = f2tf32(k0 ? b1p[c0i] : 0.f);
                ax[mi][kt][2] = f2tf32(k1 ? b0p[c1i] : 0.f);
                ax[mi][kt][3] = f2tf32(k1 ? b1p[c1i] : 0.f);
            }
        }
    }
    __syncthreads();   // s_Af ready

    const uint32_t* afu = reinterpret_cast<const uint32_t*>(s_Af);
    uint32_t* xmw = reinterpret_cast<uint32_t*>(s_xm);

    // ldmatrix base addresses (bytes)
    const uint32_t xm_sa = (uint32_t)__cvta_generic_to_shared(s_xm);
    const uint32_t w_sa  = (uint32_t)__cvta_generic_to_shared(s_w);
    const uint32_t addrA = xm_sa
        + (((ctq*16 + (lane & 15))*XMS + ((lane >> 4) << 2)) << 2);
    const uint32_t addrB = w_sa
        + (((oh*32 + ((lane >> 4) << 3) + (lane & 7))*WST
            + (((lane >> 3) & 1) << 2)) << 2);

    float dY[4][4];
    #pragma unroll
    for (int nt = 0; nt < 4; nt++)
        #pragma unroll
        for (int j = 0; j < 4; j++) dY[nt][j] = 0.f;

    for (int s = 0; s < SS; s++) {
        if (s) __syncthreads();
        // stage W_s: [o][k], float4 coalesced
        {
            const float4* wg = reinterpret_cast<const float4*>(
                g_wdT + s*(OCn*CC));
            for (int idx = tid; idx < OCn*CC/4; idx += 256) {
                int o = idx >> 4, c4 = (idx & 15) << 2;
                *reinterpret_cast<float4*>(&s_w[o*WST + c4]) = wg[idx];
            }
        }

        // ---- GEMM1 via mma: wt outer, B-frags loaded once, mi inner ----
        #pragma unroll
        for (int wt = 0; wt < 4; wt++) {
            uint32_t bq[4][2];
            #pragma unroll
            for (int kt = 0; kt < 4; kt++) {
                int fb = (((s*4 + kt)*4 + wt)*2)*32 + lane;
                bq[kt][0] = afu[fb];
                bq[kt][1] = afu[fb + 32];
            }
            #pragma unroll
            for (int mi = 0; mi < 2; mi++) {
                const int c0 = (oh + 2*mi)*16;
                float d[4] = {0.f, 0.f, 0.f, 0.f};
                #pragma unroll
                for (int kt = 0; kt < 4; kt++)
                    mma_tf32(d, ax[mi][kt][0], ax[mi][kt][1],
                                ax[mi][kt][2], ax[mi][kt][3],
                                bq[kt][0], bq[kt][1]);
                int w0  = wt*8 + 2*tc;
                int lc0 = tl*VV + w0 - coff;
                if (w0 < VV && lc0 >= 0 && lc0 < CT) {
                    xmw[lc0*XMS + c0 + gr]     = f2tf32(d[0]);
                    xmw[lc0*XMS + c0 + gr + 8] = f2tf32(d[2]);
                }
                int w1  = w0 + 1;
                int lc1 = lc0 + 1;
                if (w1 < VV && lc1 >= 0 && lc1 < CT) {
                    xmw[lc1*XMS + c0 + gr]     = f2tf32(d[1]);
                    xmw[lc1*XMS + c0 + gr + 8] = f2tf32(d[3]);
                }
            }
        }
        __syncthreads();

        // ---- GEMM2 via mma: K = 64 (this s); frags via ldmatrix ----
        #pragma unroll 2
        for (int kq = 0; kq < 8; kq++) {
            const uint32_t koff = (uint32_t)(kq*8) << 2;
            uint32_t a[4], b01[4], b23[4];
            ldsm4(a,   addrA + koff);
            ldsm4(b01, addrB + koff);
            ldsm4(b23, addrB + (16*WST << 2) + koff);
            mma_tf32(dY[0], a[0], a[1], a[2], a[3], b01[0], b01[1]);
            mma_tf32(dY[1], a[0], a[1], a[2], a[3], b01[2], b01[3]);
            mma_tf32(dY[2], a[0], a[1], a[2], a[3], b23[0], b23[1]);
            mma_tf32(dY[3], a[0], a[1], a[2], a[3], b23[2], b23[3]);
        }
    }

    // ---- epilogue: transpose through smem, coalesced I/O ----
    __syncthreads();              // GEMM2 done; s_xm reusable as s_out[o][68]
    float* s_out = s_xm;
    {
        const int row0 = ctq*16 + gr;
        #pragma unroll
        for (int nt = 0; nt < 4; nt++) {
            int oe = oh*32 + nt*8 + 2*tc;
            s_out[(oe    )*XMS + row0    ] = dY[nt][0];
            s_out[(oe + 1)*XMS + row0    ] = dY[nt][1];
            s_out[(oe    )*XMS + row0 + 8] = dY[nt][2];
            s_out[(oe + 1)*XMS + row0 + 8] = dY[nt][3];
        }
    }
    __syncthreads();
    {
        const int o  = tid >> 2;            // 0..63
        const int cg = (tid & 3) * 16;      // col strip base within block
        const float off = s_off[o];
        const float* xr  = xn + (size_t)o*NCOL + cbase + cg;
        float* orow = out + (size_t)n*(CC*NCOL) + (size_t)o*NCOL + cbase + cg;
        if (cbase + CT <= NCOL) {
            #pragma unroll
            for (int j = 0; j < 4; j++) {
                float4 yv = *reinterpret_cast<const float4*>(
                    &s_out[o*XMS + cg + 4*j]);
                float4 rv = *reinterpret_cast<const float4*>(xr + 4*j);
                float4 ov;
                ov.x = fmaxf(yv.x + off + rv.x, 0.f);
                ov.y = fmaxf(yv.y + off + rv.y, 0.f);
                ov.z = fmaxf(yv.z + off + rv.z, 0.f);
                ov.w = fmaxf(yv.w + off + rv.w, 0.f);
                *reinterpret_cast<float4*>(orow + 4*j) = ov;
            }
        } else {
            for (int j = 0; j < 16; j++) {
                if (cbase + cg + j < NCOL) {
                    float v = s_out[o*XMS + cg + j] + off + xr[j];
                    orow[j] = fmaxf(v, 0.f);
                }
            }
        }
    }
}

// ---------------------------------------------------------------------------
extern "C" void kernel_launch(void* const* d_in, const int* in_sizes, int n_in,
                              void* d_out, int out_size)
{
    const float* x     = (const float*)d_in[0];
    const float* A     = (const float*)d_in[1];
    const float* alpha = (const float*)d_in[2];
    const float* caw   = (const float*)d_in[3];
    const float* cab   = (const float*)d_in[4];
    const float* cbw   = (const float*)d_in[5];
    const float* cbb   = (const float*)d_in[6];
    const float* bag   = (const float*)d_in[7];
    const float* babt  = (const float*)d_in[8];
    const float* bam   = (const float*)d_in[9];
    const float* bav   = (const float*)d_in[10];
    const float* bbg   = (const float*)d_in[11];
    const float* bbbt  = (const float*)d_in[12];
    const float* bbm   = (const float*)d_in[13];
    const float* bbv   = (const float*)d_in[14];
    const float* cdw   = (const float*)d_in[15];
    const float* cdb   = (const float*)d_in[16];
    const float* bng   = (const float*)d_in[17];
    const float* bnb   = (const float*)d_in[18];
    const float* bnm   = (const float*)d_in[19];
    const float* bnv   = (const float*)d_in[20];
    float* out = (float*)d_out;

    const int smemB = (CT*XMS + OCn*WST + 96*32 + 64) * sizeof(float);
    cudaFuncSetAttribute(kB, cudaFuncAttributeMaxDynamicSharedMemorySize, smemB);

    // 4 launches: kB is the 4th (ncu capture slot)
    kW<<<(SS*OCn*CC + 255)/256, 256>>>(cdw, cdb, bng, bnb, bnm, bnv);
    kConvM<<<dim3(MCH, SS, NN), 256>>>(x, caw, cab, cbw, cbb,
                                       bag, babt, bam, bav,
                                       bbg, bbbt, bbm, bbv);
    kA2<<<(NN*96*32 + 255)/256, 256>>>(A, alpha);
    kB<<<dim3(NTBL, NN), 256, smemB>>>(x, out);
}

// round 16
// speedup vs baseline: 1.0606x; 1.0606x over previous
#include <cuda_runtime.h>
#include <cuda_bf16.h>
#include <cstdint>

#define EPSF 1e-5f

// Problem dims
#define NN  64
#define CC  64
#define TD  300
#define VV  25
#define SS  3
#define ICn 16
#define OCn 64
#define NCOL (TD*VV)          // 7500

// kConvM tiling
#define TCB   20
#define MCH   (TD/TCB)        // 15 chunks (also M split-k partials)
#define COLSB (TCB*VV)        // 500

// kB tiling
#define CT    64                      // cols per block
#define NTBL  ((NCOL + CT - 1)/CT)    // 118
#define XMS   68                      // xm row stride
#define WST   68                      // W row stride ([o][k], LDSM conflict-free)

typedef unsigned long long u64;

__device__ float g_Mpart[MCH*NN*SS*VV*VV];
__device__ float g_Afrag[(size_t)NN*96*32];  // A_adp in mma frag layout, tf32
__device__ float g_wdT  [SS*OCn*CC];         // [s][o][c], BN-scaled, tf32 bits
__device__ float g_off  [OCn];

__device__ __forceinline__ float tanh_fast(float x) {
    float y;
    asm("tanh.approx.f32 %0, %1;" : "=f"(y) : "f"(x));
    return y;
}
__device__ __forceinline__ uint32_t f2tf32(float x) {
    uint32_t u;
    asm("cvt.rna.tf32.f32 %0, %1;" : "=r"(u) : "f"(x));
    return u;
}
__device__ __forceinline__ uint32_t prmt(uint32_t a, uint32_t b, uint32_t sel) {
    uint32_t d;
    asm("prmt.b32 %0, %1, %2, %3;" : "=r"(d) : "r"(a), "r"(b), "r"(sel));
    return d;
}
__device__ __forceinline__ uint32_t bfpack(float lo, float hi) {
    __nv_bfloat162 h = __floats2bfloat162_rn(lo, hi);
    return *reinterpret_cast<uint32_t*>(&h);
}
__device__ __forceinline__ void mma_tf32(float d[4],
    uint32_t a0, uint32_t a1, uint32_t a2, uint32_t a3,
    uint32_t b0, uint32_t b1)
{
    asm volatile(
        "mma.sync.aligned.m16n8k8.row.col.f32.tf32.tf32.f32 "
        "{%0,%1,%2,%3}, {%4,%5,%6,%7}, {%8,%9}, {%0,%1,%2,%3};\n"
        : "+f"(d[0]), "+f"(d[1]), "+f"(d[2]), "+f"(d[3])
        : "r"(a0), "r"(a1), "r"(a2), "r"(a3), "r"(b0), "r"(b1));
}
__device__ __forceinline__ void mma_bf16(float d[4],
    uint32_t a0, uint32_t a1, uint32_t a2, uint32_t a3,
    uint32_t b0, uint32_t b1)
{
    asm volatile(
        "mma.sync.aligned.m16n8k16.row.col.f32.bf16.bf16.f32 "
        "{%0,%1,%2,%3}, {%4,%5,%6,%7}, {%8,%9}, {%0,%1,%2,%3};\n"
        : "+f"(d[0]), "+f"(d[1]), "+f"(d[2]), "+f"(d[3])
        : "r"(a0), "r"(a1), "r"(a2), "r"(a3), "r"(b0), "r"(b1));
}
__device__ __forceinline__ void ldsm4(uint32_t r[4], uint32_t addr)
{
    asm volatile(
        "ldmatrix.sync.aligned.m8n8.x4.shared.b16 {%0,%1,%2,%3}, [%4];"
        : "=r"(r[0]), "=r"(r[1]), "=r"(r[2]), "=r"(r[3]) : "r"(addr));
}

// ---------------------------------------------------------------------------
// kConvM: per (chunk of 20 t, s, n):
//  Phase 1 (tf32 mma): conv + tanh -> bf16 mma fragments in smem.
//  Phase 2 (bf16 mma): partial M over 20 k16-steps; reduction; g_Mpart.
// ---------------------------------------------------------------------------
__global__ __launch_bounds__(256, 2) void kConvM(
    const float* __restrict__ x,
    const float* __restrict__ wa, const float* __restrict__ ba,
    const float* __restrict__ wb, const float* __restrict__ bb,
    const float* __restrict__ gag, const float* __restrict__ gab,
    const float* __restrict__ gam, const float* __restrict__ gav,
    const float* __restrict__ gbg, const float* __restrict__ gbb,
    const float* __restrict__ gbm, const float* __restrict__ gbv)
{
    __shared__ __align__(16) uint32_t s_fr[2*TCB*256];
    __shared__ float s_sh[32];

    uint32_t* s_aF = s_fr;
    uint32_t* s_bF = s_fr + TCB*256;
    float*    s_wf = reinterpret_cast<float*>(s_fr);

    const int tid  = threadIdx.x;
    const int wid  = tid >> 5;
    const int lane = tid & 31;
    const int gr   = lane >> 2;
    const int tc   = lane & 3;
    const int chunk = blockIdx.x;
    const int s     = blockIdx.y;
    const int n     = blockIdx.z;

    for (int idx = tid; idx < 32*CC; idx += 256) {
        int io = idx >> 6, c = idx & 63;
        int i  = io & 15;
        bool isB = io >= 16;
        float g  = isB ? gbg[s*ICn+i] : gag[s*ICn+i];
        float vv = isB ? gbv[s*ICn+i] : gav[s*ICn+i];
        float wv = isB ? wb[s*ICn*CC + i*CC + c] : wa[s*ICn*CC + i*CC + c];
        float sc = g * rsqrtf(vv + EPSF);
        s_wf[io*68 + c] = __uint_as_float(f2tf32(wv * sc));
    }
    if (tid < 32) {
        int i = tid & 15;
        bool isB = tid >= 16;
        float g  = isB ? gbg[s*ICn+i] : gag[s*ICn+i];
        float vv = isB ? gbv[s*ICn+i] : gav[s*ICn+i];
        float bs = isB ? bb[s*ICn+i]  : ba[s*ICn+i];
        float mn = isB ? gbm[s*ICn+i] : gam[s*ICn+i];
        float bt = isB ? gbb[s*ICn+i] : gab[s*ICn+i];
        float sc = g * rsqrtf(vv + EPSF);
        s_sh[tid] = (bs - mn) * sc + bt;
    }
    __syncthreads();

    const uint32_t* wfu = reinterpret_cast<const uint32_t*>(s_wf);
    uint32_t af[2][8][4];
    #pragma unroll
    for (int mi = 0; mi < 2; mi++)
        #pragma unroll
        for (int kt = 0; kt < 8; kt++) {
            int r0 = (mi*16 + gr)*68 + kt*8 + tc;
            af[mi][kt][0] = wfu[r0];
            af[mi][kt][1] = wfu[r0 + 8*68];
            af[mi][kt][2] = wfu[r0 + 4];
            af[mi][kt][3] = wfu[r0 + 8*68 + 4];
        }
    const float sha0 = s_sh[gr],      sha8 = s_sh[gr + 8];
    const float shb0 = s_sh[16 + gr], shb8 = s_sh[24 + gr];
    __syncthreads();

    for (int idx = tid; idx < 2*TCB*256; idx += 256) s_fr[idx] = 0u;
    __syncthreads();

    const float* xn = x + (size_t)n*(CC*NCOL);
    const int lwbase = wid*64;
    const int tck = gr >> 1;
    const bool evenGr = ((gr & 1) == 0);

    #pragma unroll 2
    for (int nt = 0; nt < 8; nt++) {
        const int n0 = nt*8;
        const int lcol = lwbase + n0 + gr;
        const bool ld  = (lcol < COLSB);
        const int colg = chunk*COLSB + lcol;

        uint32_t bf[8][2];
        const float* xp = xn + colg;
        #pragma unroll
        for (int kt = 0; kt < 8; kt++) {
            float v0 = ld ? xp[(size_t)(kt*8 + tc)*NCOL]     : 0.f;
            float v1 = ld ? xp[(size_t)(kt*8 + tc + 4)*NCOL] : 0.f;
            bf[kt][0] = f2tf32(v0);
            bf[kt][1] = f2tf32(v1);
        }

        float da[4] = {0.f, 0.f, 0.f, 0.f};
        float dbv[4] = {0.f, 0.f, 0.f, 0.f};
        #pragma unroll
        for (int kt = 0; kt < 8; kt++) {
            mma_tf32(da,  af[0][kt][0], af[0][kt][1], af[0][kt][2], af[0][kt][3],
                     bf[kt][0], bf[kt][1]);
            mma_tf32(dbv, af[1][kt][0], af[1][kt][1], af[1][kt][2], af[1][kt][3],
                     bf[kt][0], bf[kt][1]);
        }

        uint32_t ha  = bfpack(tanh_fast(da[0]  + sha0), tanh_fast(da[1]  + sha0));
        uint32_t ha8 = bfpack(tanh_fast(da[2]  + sha8), tanh_fast(da[3]  + sha8));
        uint32_t hb  = bfpack(tanh_fast(dbv[0] + shb0), tanh_fast(dbv[1] + shb0));
        uint32_t hb8 = bfpack(tanh_fast(dbv[2] + shb8), tanh_fast(dbv[3] + shb8));

        uint32_t pa  = __shfl_xor_sync(0xffffffffu, ha,  4);
        uint32_t pa8 = __shfl_xor_sync(0xffffffffu, ha8, 4);
        uint32_t pb  = __shfl_xor_sync(0xffffffffu, hb,  4);
        uint32_t pb8 = __shfl_xor_sync(0xffffffffu, hb8, 4);

        const int lc0 = lwbase + n0 + 2*tc;

        if (evenGr) {
            uint32_t wlo0 = prmt(ha,  pa,  0x5410);
            uint32_t whi0 = prmt(ha8, pa8, 0x5410);
            uint32_t wlo1 = prmt(ha,  pa,  0x7632);
            uint32_t whi1 = prmt(ha8, pa8, 0x7632);
            #pragma unroll
            for (int cc2 = 0; cc2 < 2; cc2++) {
                int lc = lc0 + cc2;
                if (lc < COLSB) {
                    int tl = lc / 25, v = lc - 25*tl;
                    int mt = v >> 4, vt = v & 15;
                    int rsel = vt >> 3, grt = vt & 7;
                    uint32_t wlo = cc2 ? wlo1 : wlo0;
                    uint32_t whi = cc2 ? whi1 : whi0;
                    s_aF[tl*256 + (mt*4 + rsel    )*32 + grt*4 + tck] = wlo;
                    s_aF[tl*256 + (mt*4 + 2 + rsel)*32 + grt*4 + tck] = whi;
                }
            }
        } else {
            uint32_t wlo0 = prmt(pb,  hb,  0x5410);
            uint32_t whi0 = prmt(pb8, hb8, 0x5410);
            uint32_t wlo1 = prmt(pb,  hb,  0x7632);
            uint32_t whi1 = prmt(pb8, hb8, 0x7632);
            #pragma unroll
            for (int cc2 = 0; cc2 < 2; cc2++) {
                int lc = lc0 + cc2;
                if (lc < COLSB) {
                    int tl = lc / 25, v = lc - 25*tl;
                    int wt = v >> 3, grw = v & 7;
                    uint32_t wlo = cc2 ? wlo1 : wlo0;
                    uint32_t whi = cc2 ? whi1 : whi0;
                    s_bF[tl*256 + (wt*2    )*32 + grw*4 + tck] = wlo;
                    s_bF[tl*256 + (wt*2 + 1)*32 + grw*4 + tck] = whi;
                }
            }
        }
    }
    __syncthreads();

    float acc[2][4][4];
    #pragma unroll
    for (int mt = 0; mt < 2; mt++)
        #pragma unroll
        for (int wt = 0; wt < 4; wt++)
            #pragma unroll
            for (int r = 0; r < 4; r++) acc[mt][wt][r] = 0.f;

    for (int ls = wid; ls < TCB; ls += 8) {
        const uint32_t* pa = s_aF + ls*256 + lane;
        const uint32_t* pb = s_bF + ls*256 + lane;
        uint32_t aw[2][4], bw[4][2];
        #pragma unroll
        for (int mt = 0; mt < 2; mt++)
            #pragma unroll
            for (int r = 0; r < 4; r++)
                aw[mt][r] = pa[(mt*4 + r)*32];
        #pragma unroll
        for (int wt = 0; wt < 4; wt++)
            #pragma unroll
            for (int r = 0; r < 2; r++)
                bw[wt][r] = pb[(wt*2 + r)*32];
        #pragma unroll
        for (int mt = 0; mt < 2; mt++)
            #pragma unroll
            for (int wt = 0; wt < 4; wt++)
                mma_bf16(acc[mt][wt], aw[mt][0], aw[mt][1], aw[mt][2], aw[mt][3],
                         bw[wt][0], bw[wt][1]);
    }
    __syncthreads();

    float* s_red = reinterpret_cast<float*>(s_fr);
    float* my = s_red + wid*1024;
    #pragma unroll
    for (int mt = 0; mt < 2; mt++)
        #pragma unroll
        for (int wt = 0; wt < 4; wt++)
            #pragma unroll
            for (int r = 0; r < 4; r++)
                my[((mt*4 + wt)*4 + r)*32 + lane] = acc[mt][wt][r];
    __syncthreads();

    #pragma unroll
    for (int rep = 0; rep < 4; rep++) {
        int pos = tid + rep*256;
        float v = 0.f;
        #pragma unroll
        for (int w8 = 0; w8 < 8; w8++)
            v += s_red[w8*1024 + pos];
        int lp  = pos & 31;
        int reg = (pos >> 5) & 3;
        int wt  = (pos >> 7) & 3;
        int mt  = pos >> 9;
        int grp = lp >> 2, tcp = lp & 3;
        int vv = mt*16 + grp + (reg >> 1)*8;
        int ww = wt*8 + 2*tcp + (reg & 1);
        if (vv < VV && ww < VV)
            g_Mpart[((size_t)chunk*NN*SS + (size_t)n*SS + s)*(VV*VV)
                    + vv*VV + ww] = v;
    }
}

// ---------------------------------------------------------------------------
// kA2: reduce partials, A_adp in kB's mma fragment layout.
// ---------------------------------------------------------------------------
__global__ void kA2(const float* __restrict__ A, const float* __restrict__ alpha)
{
    int idx = blockIdx.x * 256 + threadIdx.x;
    if (idx >= NN*96*32) return;
    int lane = idx & 31;
    int r    = (idx >> 5) % 96;
    int n    = idx / (96*32);
    int reg = r & 1;
    int wt  = (r >> 1) & 3;
    int kt  = (r >> 3) & 3;
    int s   = r >> 5;
    int v = kt*8 + (lane & 3) + reg*4;
    int w = wt*8 + (lane >> 2);
    float val = 0.f;
    if (v < VV && w < VV) {
        int mi = (n*SS + s)*(VV*VV) + v*VV + w;
        float m = 0.f;
        #pragma unroll
        for (int ch = 0; ch < MCH; ch++)
            m += g_Mpart[ch*(NN*SS*VV*VV) + mi];
        val = A[s*(VV*VV) + v*VV + w]
            + tanhf(m * (1.f/(float)(ICn*TD))) * alpha[0];
    }
    g_Afrag[idx] = __uint_as_float(f2tf32(val));
}

// ---------------------------------------------------------------------------
// kW: W -> [s][o][c] (native layout), BN scale folded, tf32-rounded. g_off.
// ---------------------------------------------------------------------------
__global__ void kW(const float* __restrict__ wd, const float* __restrict__ db,
                   const float* __restrict__ bng, const float* __restrict__ bnb,
                   const float* __restrict__ bnm, const float* __restrict__ bnv)
{
    int idx = blockIdx.x * 256 + threadIdx.x;
    if (idx < SS*OCn*CC) {
        int o = (idx >> 6) & 63;
        float sc = bng[o] * rsqrtf(bnv[o] + EPSF);
        g_wdT[idx] = __uint_as_float(f2tf32(wd[idx] * sc));
    }
    if (blockIdx.x == 0 && threadIdx.x < OCn) {
        int o = threadIdx.x;
        float sc = bng[o] * rsqrtf(bnv[o] + EPSF);
        float ds = db[o] + db[OCn + o] + db[2*OCn + o];
        g_off[o] = (ds - bnm[o]) * sc + bnb[o];
    }
}

// ---------------------------------------------------------------------------
// kB: block = (64-col tile, n), 4 blocks/SM. For each s:
//   GEMM1 (mma tf32): xm[col][c]; B-frags loaded once per wt (mi inner)
//   GEMM2 (mma tf32): D[col][o] += xm @ W_s; fragments via ldmatrix.x4
// Epilogue: scattered per-fragment stores + residual (R14 form).
// ---------------------------------------------------------------------------
__global__ __launch_bounds__(256, 4) void kB(
    const float* __restrict__ x,
    float* __restrict__ out)
{
    extern __shared__ float sm[];
    float* s_xm  = sm;                  // [64][68]  tf32 bits
    float* s_w   = s_xm + CT*XMS;       // [64][68]  tf32 bits, [o][k] per s
    float* s_Af  = s_w  + OCn*WST;      // [96][32]  A_adp frags, tf32
    float* s_off = s_Af + 96*32;        // [64]

    const int tid  = threadIdx.x;
    const int wid  = tid >> 5;
    const int lane = tid & 31;
    const int gr   = lane >> 2;
    const int tc   = lane & 3;
    const int blk  = blockIdx.x;
    const int n    = blockIdx.y;
    const int cbase = blk * CT;
    const int t0    = cbase / VV;
    const int coff  = cbase - t0*VV;

    const float* xn = x + (size_t)n*(CC*NCOL);

    // ---- prologue staging ----
    {
        const float4* ag = reinterpret_cast<const float4*>(
            g_Afrag + (size_t)n*(96*32));
        float4* as = reinterpret_cast<float4*>(s_Af);
        for (int idx = tid; idx < 96*32/4; idx += 256)
            as[idx] = ag[idx];
    }
    if (tid < OCn) s_off[tid] = g_off[tid];

    // warp roles
    const int tl = wid & 3;
    const int oh = wid >> 2;
    const int ctq = wid & 3;

    // x A-fragments in registers (s-invariant)
    uint32_t ax[2][4][4];
    {
        const int colB = (t0 + tl)*VV;
        #pragma unroll
        for (int mi = 0; mi < 2; mi++) {
            const int r0 = (oh + 2*mi)*16 + gr;
            const float* b0p = xn + (size_t)r0*NCOL;
            const float* b1p = b0p + (size_t)8*NCOL;
            #pragma unroll
            for (int kt = 0; kt < 4; kt++) {
                int c0i = colB + kt*8 + tc;
                int c1i = c0i + 4;
                bool k0 = (c0i < NCOL);
                bool k1 = (c1i < NCOL);
                ax[mi][kt][0] = f2tf32(k0 ? b0p[c0i] : 0.f);
                ax[mi][kt][1] = f2tf32(k0 ? b1p[c0i] : 0.f);
                ax[mi][kt][2] = f2tf32(k1 ? b0p[c1i] : 0.f);
                ax[mi][kt][3] = f2tf32(k1 ? b1p[c1i] : 0.f);
            }
        }
    }
    __syncthreads();   // s_Af ready

    const uint32_t* afu = reinterpret_cast<const uint32_t*>(s_Af);
    uint32_t* xmw = reinterpret_cast<uint32_t*>(s_xm);

    // ldmatrix base addresses (bytes)
    const uint32_t xm_sa = (uint32_t)__cvta_generic_to_shared(s_xm);
    const uint32_t w_sa  = (uint32_t)__cvta_generic_to_shared(s_w);
    const uint32_t addrA = xm_sa
        + (((ctq*16 + (lane & 15))*XMS + ((lane >> 4) << 2)) << 2);
    const uint32_t addrB = w_sa
        + (((oh*32 + ((lane >> 4) << 3) + (lane & 7))*WST
            + (((lane >> 3) & 1) << 2)) << 2);

    float dY[4][4];
    #pragma unroll
    for (int nt = 0; nt < 4; nt++)
        #pragma unroll
        for (int j = 0; j < 4; j++) dY[nt][j] = 0.f;

    for (int s = 0; s < SS; s++) {
        if (s) __syncthreads();
        // stage W_s: [o][k], float4 coalesced
        {
            const float4* wg = reinterpret_cast<const float4*>(
                g_wdT + s*(OCn*CC));
            for (int idx = tid; idx < OCn*CC/4; idx += 256) {
                int o = idx >> 4, c4 = (idx & 15) << 2;
                *reinterpret_cast<float4*>(&s_w[o*WST + c4]) = wg[idx];
            }
        }

        // ---- GEMM1 via mma: wt outer, B-frags loaded once, mi inner ----
        #pragma unroll
        for (int wt = 0; wt < 4; wt++) {
            uint32_t bq[4][2];
            #pragma unroll
            for (int kt = 0; kt < 4; kt++) {
                int fb = (((s*4 + kt)*4 + wt)*2)*32 + lane;
                bq[kt][0] = afu[fb];
                bq[kt][1] = afu[fb + 32];
            }
            #pragma unroll
            for (int mi = 0; mi < 2; mi++) {
                const int c0 = (oh + 2*mi)*16;
                float d[4] = {0.f, 0.f, 0.f, 0.f};
                #pragma unroll
                for (int kt = 0; kt < 4; kt++)
                    mma_tf32(d, ax[mi][kt][0], ax[mi][kt][1],
                                ax[mi][kt][2], ax[mi][kt][3],
                                bq[kt][0], bq[kt][1]);
                int w0  = wt*8 + 2*tc;
                int lc0 = tl*VV + w0 - coff;
                if (w0 < VV && lc0 >= 0 && lc0 < CT) {
                    xmw[lc0*XMS + c0 + gr]     = f2tf32(d[0]);
                    xmw[lc0*XMS + c0 + gr + 8] = f2tf32(d[2]);
                }
                int w1  = w0 + 1;
                int lc1 = lc0 + 1;
                if (w1 < VV && lc1 >= 0 && lc1 < CT) {
                    xmw[lc1*XMS + c0 + gr]     = f2tf32(d[1]);
                    xmw[lc1*XMS + c0 + gr + 8] = f2tf32(d[3]);
                }
            }
        }
        __syncthreads();

        // ---- GEMM2 via mma: K = 64 (this s); frags via ldmatrix ----
        #pragma unroll 2
        for (int kq = 0; kq < 8; kq++) {
            const uint32_t koff = (uint32_t)(kq*8) << 2;
            uint32_t a[4], b01[4], b23[4];
            ldsm4(a,   addrA + koff);
            ldsm4(b01, addrB + koff);
            ldsm4(b23, addrB + (16*WST << 2) + koff);
            mma_tf32(dY[0], a[0], a[1], a[2], a[3], b01[0], b01[1]);
            mma_tf32(dY[1], a[0], a[1], a[2], a[3], b01[2], b01[3]);
            mma_tf32(dY[2], a[0], a[1], a[2], a[3], b23[0], b23[1]);
            mma_tf32(dY[3], a[0], a[1], a[2], a[3], b23[2], b23[3]);
        }
    }

    // ---- epilogue (R14 scattered form) ----
    {
        const int row0 = ctq*16 + gr;
        const int row1 = row0 + 8;
        const int colg0 = cbase + row0;
        const int colg1 = cbase + row1;
        const bool ok0 = (colg0 < NCOL);
        const bool ok1 = (colg1 < NCOL);
        float* on = out + (size_t)n*(CC*NCOL);
        #pragma unroll
        for (int nt = 0; nt < 4; nt++) {
            int oe = oh*32 + nt*8 + 2*tc;
            int oo = oe + 1;
            float offe = s_off[oe], offo = s_off[oo];
            if (ok0) {
                float v0 = dY[nt][0] + offe + xn[(size_t)oe*NCOL + colg0];
                float v1 = dY[nt][1] + offo + xn[(size_t)oo*NCOL + colg0];
                on[(size_t)oe*NCOL + colg0] = fmaxf(v0, 0.f);
                on[(size_t)oo*NCOL + colg0] = fmaxf(v1, 0.f);
            }
            if (ok1) {
                float v2 = dY[nt][2] + offe + xn[(size_t)oe*NCOL + colg1];
                float v3 = dY[nt][3] + offo + xn[(size_t)oo*NCOL + colg1];
                on[(size_t)oe*NCOL + colg1] = fmaxf(v2, 0.f);
                on[(size_t)oo*NCOL + colg1] = fmaxf(v3, 0.f);
            }
        }
    }
}

// ---------------------------------------------------------------------------
extern "C" void kernel_launch(void* const* d_in, const int* in_sizes, int n_in,
                              void* d_out, int out_size)
{
    const float* x     = (const float*)d_in[0];
    const float* A     = (const float*)d_in[1];
    const float* alpha = (const float*)d_in[2];
    const float* caw   = (const float*)d_in[3];
    const float* cab   = (const float*)d_in[4];
    const float* cbw   = (const float*)d_in[5];
    const float* cbb   = (const float*)d_in[6];
    const float* bag   = (const float*)d_in[7];
    const float* babt  = (const float*)d_in[8];
    const float* bam   = (const float*)d_in[9];
    const float* bav   = (const float*)d_in[10];
    const float* bbg   = (const float*)d_in[11];
    const float* bbbt  = (const float*)d_in[12];
    const float* bbm   = (const float*)d_in[13];
    const float* bbv   = (const float*)d_in[14];
    const float* cdw   = (const float*)d_in[15];
    const float* cdb   = (const float*)d_in[16];
    const float* bng   = (const float*)d_in[17];
    const float* bnb   = (const float*)d_in[18];
    const float* bnm   = (const float*)d_in[19];
    const float* bnv   = (const float*)d_in[20];
    float* out = (float*)d_out;

    const int smemB = (CT*XMS + OCn*WST + 96*32 + 64) * sizeof(float);
    cudaFuncSetAttribute(kB, cudaFuncAttributeMaxDynamicSharedMemorySize, smemB);

    // 4 launches: kB is the 4th (ncu capture slot)
    kW<<<(SS*OCn*CC + 255)/256, 256>>>(cdw, cdb, bng, bnb, bnm, bnv);
    kConvM<<<dim3(MCH, SS, NN), 256>>>(x, caw, cab, cbw, cbb,
                                       bag, babt, bam, bav,
                                       bbg, bbbt, bbm, bbv);
    kA2<<<(NN*96*32 + 255)/256, 256>>>(A, alpha);
    kB<<<dim3(NTBL, NN), 256, smemB>>>(x, out);
}

// round 17
// speedup vs baseline: 1.0985x; 1.0357x over previous
#include <cuda_runtime.h>
#include <cuda_bf16.h>
#include <cstdint>

#define EPSF 1e-5f

// Problem dims
#define NN  64
#define CC  64
#define TD  300
#define VV  25
#define SS  3
#define ICn 16
#define OCn 64
#define NCOL (TD*VV)          // 7500

// kConvM tiling
#define TCB   20
#define MCH   (TD/TCB)        // 15 chunks (also M split-k partials)
#define COLSB (TCB*VV)        // 500

// kB tiling
#define CT    64                      // cols per block
#define NTBL  ((NCOL + CT - 1)/CT)    // 118
#define XMS   68                      // xm row stride
#define WST   68                      // W row stride ([o][k], LDSM conflict-free)

typedef unsigned long long u64;

__device__ float g_Mpart[MCH*NN*SS*VV*VV];
// A_adp in mma frag layout, tf32, frag word-pairs adjacent:
//   g_Afrag[n][r48][lane][2],  r48 = (s*4+kt)*4+wt
__device__ float g_Afrag[(size_t)NN*48*32*2];
__device__ float g_wdT  [SS*OCn*CC];         // [s][o][c], BN-scaled, tf32 bits
__device__ float g_off  [OCn];

__device__ __forceinline__ float tanh_fast(float x) {
    float y;
    asm("tanh.approx.f32 %0, %1;" : "=f"(y) : "f"(x));
    return y;
}
__device__ __forceinline__ uint32_t f2tf32(float x) {
    uint32_t u;
    asm("cvt.rna.tf32.f32 %0, %1;" : "=r"(u) : "f"(x));
    return u;
}
__device__ __forceinline__ uint32_t prmt(uint32_t a, uint32_t b, uint32_t sel) {
    uint32_t d;
    asm("prmt.b32 %0, %1, %2, %3;" : "=r"(d) : "r"(a), "r"(b), "r"(sel));
    return d;
}
__device__ __forceinline__ uint32_t bfpack(float lo, float hi) {
    __nv_bfloat162 h = __floats2bfloat162_rn(lo, hi);
    return *reinterpret_cast<uint32_t*>(&h);
}
__device__ __forceinline__ void mma_tf32(float d[4],
    uint32_t a0, uint32_t a1, uint32_t a2, uint32_t a3,
    uint32_t b0, uint32_t b1)
{
    asm volatile(
        "mma.sync.aligned.m16n8k8.row.col.f32.tf32.tf32.f32 "
        "{%0,%1,%2,%3}, {%4,%5,%6,%7}, {%8,%9}, {%0,%1,%2,%3};\n"
        : "+f"(d[0]), "+f"(d[1]), "+f"(d[2]), "+f"(d[3])
        : "r"(a0), "r"(a1), "r"(a2), "r"(a3), "r"(b0), "r"(b1));
}
__device__ __forceinline__ void mma_bf16(float d[4],
    uint32_t a0, uint32_t a1, uint32_t a2, uint32_t a3,
    uint32_t b0, uint32_t b1)
{
    asm volatile(
        "mma.sync.aligned.m16n8k16.row.col.f32.bf16.bf16.f32 "
        "{%0,%1,%2,%3}, {%4,%5,%6,%7}, {%8,%9}, {%0,%1,%2,%3};\n"
        : "+f"(d[0]), "+f"(d[1]), "+f"(d[2]), "+f"(d[3])
        : "r"(a0), "r"(a1), "r"(a2), "r"(a3), "r"(b0), "r"(b1));
}
__device__ __forceinline__ void ldsm4(uint32_t r[4], uint32_t addr)
{
    asm volatile(
        "ldmatrix.sync.aligned.m8n8.x4.shared.b16 {%0,%1,%2,%3}, [%4];"
        : "=r"(r[0]), "=r"(r[1]), "=r"(r[2]), "=r"(r[3]) : "r"(addr));
}

// ---------------------------------------------------------------------------
// kConvM: per (chunk of 20 t, s, n):
//  Phase 1 (tf32 mma): conv + tanh -> bf16 mma fragments in smem.
//  Phase 2 (bf16 mma): partial M over 20 k16-steps; reduction; g_Mpart.
// ---------------------------------------------------------------------------
__global__ __launch_bounds__(256, 2) void kConvM(
    const float* __restrict__ x,
    const float* __restrict__ wa, const float* __restrict__ ba,
    const float* __restrict__ wb, const float* __restrict__ bb,
    const float* __restrict__ gag, const float* __restrict__ gab,
    const float* __restrict__ gam, const float* __restrict__ gav,
    const float* __restrict__ gbg, const float* __restrict__ gbb,
    const float* __restrict__ gbm, const float* __restrict__ gbv)
{
    __shared__ __align__(16) uint32_t s_fr[2*TCB*256];
    __shared__ float s_sh[32];

    uint32_t* s_aF = s_fr;
    uint32_t* s_bF = s_fr + TCB*256;
    float*    s_wf = reinterpret_cast<float*>(s_fr);

    const int tid  = threadIdx.x;
    const int wid  = tid >> 5;
    const int lane = tid & 31;
    const int gr   = lane >> 2;
    const int tc   = lane & 3;
    const int chunk = blockIdx.x;
    const int s     = blockIdx.y;
    const int n     = blockIdx.z;

    for (int idx = tid; idx < 32*CC; idx += 256) {
        int io = idx >> 6, c = idx & 63;
        int i  = io & 15;
        bool isB = io >= 16;
        float g  = isB ? gbg[s*ICn+i] : gag[s*ICn+i];
        float vv = isB ? gbv[s*ICn+i] : gav[s*ICn+i];
        float wv = isB ? wb[s*ICn*CC + i*CC + c] : wa[s*ICn*CC + i*CC + c];
        float sc = g * rsqrtf(vv + EPSF);
        s_wf[io*68 + c] = __uint_as_float(f2tf32(wv * sc));
    }
    if (tid < 32) {
        int i = tid & 15;
        bool isB = tid >= 16;
        float g  = isB ? gbg[s*ICn+i] : gag[s*ICn+i];
        float vv = isB ? gbv[s*ICn+i] : gav[s*ICn+i];
        float bs = isB ? bb[s*ICn+i]  : ba[s*ICn+i];
        float mn = isB ? gbm[s*ICn+i] : gam[s*ICn+i];
        float bt = isB ? gbb[s*ICn+i] : gab[s*ICn+i];
        float sc = g * rsqrtf(vv + EPSF);
        s_sh[tid] = (bs - mn) * sc + bt;
    }
    __syncthreads();

    const uint32_t* wfu = reinterpret_cast<const uint32_t*>(s_wf);
    uint32_t af[2][8][4];
    #pragma unroll
    for (int mi = 0; mi < 2; mi++)
        #pragma unroll
        for (int kt = 0; kt < 8; kt++) {
            int r0 = (mi*16 + gr)*68 + kt*8 + tc;
            af[mi][kt][0] = wfu[r0];
            af[mi][kt][1] = wfu[r0 + 8*68];
            af[mi][kt][2] = wfu[r0 + 4];
            af[mi][kt][3] = wfu[r0 + 8*68 + 4];
        }
    const float sha0 = s_sh[gr],      sha8 = s_sh[gr + 8];
    const float shb0 = s_sh[16 + gr], shb8 = s_sh[24 + gr];
    __syncthreads();

    for (int idx = tid; idx < 2*TCB*256; idx += 256) s_fr[idx] = 0u;
    __syncthreads();

    const float* xn = x + (size_t)n*(CC*NCOL);
    const int lwbase = wid*64;
    const int tck = gr >> 1;
    const bool evenGr = ((gr & 1) == 0);

    #pragma unroll 2
    for (int nt = 0; nt < 8; nt++) {
        const int n0 = nt*8;
        const int lcol = lwbase + n0 + gr;
        const bool ld  = (lcol < COLSB);
        const int colg = chunk*COLSB + lcol;

        uint32_t bf[8][2];
        const float* xp = xn + colg;
        #pragma unroll
        for (int kt = 0; kt < 8; kt++) {
            float v0 = ld ? xp[(size_t)(kt*8 + tc)*NCOL]     : 0.f;
            float v1 = ld ? xp[(size_t)(kt*8 + tc + 4)*NCOL] : 0.f;
            bf[kt][0] = f2tf32(v0);
            bf[kt][1] = f2tf32(v1);
        }

        float da[4] = {0.f, 0.f, 0.f, 0.f};
        float dbv[4] = {0.f, 0.f, 0.f, 0.f};
        #pragma unroll
        for (int kt = 0; kt < 8; kt++) {
            mma_tf32(da,  af[0][kt][0], af[0][kt][1], af[0][kt][2], af[0][kt][3],
                     bf[kt][0], bf[kt][1]);
            mma_tf32(dbv, af[1][kt][0], af[1][kt][1], af[1][kt][2], af[1][kt][3],
                     bf[kt][0], bf[kt][1]);
        }

        uint32_t ha  = bfpack(tanh_fast(da[0]  + sha0), tanh_fast(da[1]  + sha0));
        uint32_t ha8 = bfpack(tanh_fast(da[2]  + sha8), tanh_fast(da[3]  + sha8));
        uint32_t hb  = bfpack(tanh_fast(dbv[0] + shb0), tanh_fast(dbv[1] + shb0));
        uint32_t hb8 = bfpack(tanh_fast(dbv[2] + shb8), tanh_fast(dbv[3] + shb8));

        uint32_t pa  = __shfl_xor_sync(0xffffffffu, ha,  4);
        uint32_t pa8 = __shfl_xor_sync(0xffffffffu, ha8, 4);
        uint32_t pb  = __shfl_xor_sync(0xffffffffu, hb,  4);
        uint32_t pb8 = __shfl_xor_sync(0xffffffffu, hb8, 4);

        const int lc0 = lwbase + n0 + 2*tc;

        if (evenGr) {
            uint32_t wlo0 = prmt(ha,  pa,  0x5410);
            uint32_t whi0 = prmt(ha8, pa8, 0x5410);
            uint32_t wlo1 = prmt(ha,  pa,  0x7632);
            uint32_t whi1 = prmt(ha8, pa8, 0x7632);
            #pragma unroll
            for (int cc2 = 0; cc2 < 2; cc2++) {
                int lc = lc0 + cc2;
                if (lc < COLSB) {
                    int tl = lc / 25, v = lc - 25*tl;
                    int mt = v >> 4, vt = v & 15;
                    int rsel = vt >> 3, grt = vt & 7;
                    uint32_t wlo = cc2 ? wlo1 : wlo0;
                    uint32_t whi = cc2 ? whi1 : whi0;
                    s_aF[tl*256 + (mt*4 + rsel    )*32 + grt*4 + tck] = wlo;
                    s_aF[tl*256 + (mt*4 + 2 + rsel)*32 + grt*4 + tck] = whi;
                }
            }
        } else {
            uint32_t wlo0 = prmt(pb,  hb,  0x5410);
            uint32_t whi0 = prmt(pb8, hb8, 0x5410);
            uint32_t wlo1 = prmt(pb,  hb,  0x7632);
            uint32_t whi1 = prmt(pb8, hb8, 0x7632);
            #pragma unroll
            for (int cc2 = 0; cc2 < 2; cc2++) {
                int lc = lc0 + cc2;
                if (lc < COLSB) {
                    int tl = lc / 25, v = lc - 25*tl;
                    int wt = v >> 3, grw = v & 7;
                    uint32_t wlo = cc2 ? wlo1 : wlo0;
                    uint32_t whi = cc2 ? whi1 : whi0;
                    s_bF[tl*256 + (wt*2    )*32 + grw*4 + tck] = wlo;
                    s_bF[tl*256 + (wt*2 + 1)*32 + grw*4 + tck] = whi;
                }
            }
        }
    }
    __syncthreads();

    float acc[2][4][4];
    #pragma unroll
    for (int mt = 0; mt < 2; mt++)
        #pragma unroll
        for (int wt = 0; wt < 4; wt++)
            #pragma unroll
            for (int r = 0; r < 4; r++) acc[mt][wt][r] = 0.f;

    for (int ls = wid; ls < TCB; ls += 8) {
        const uint32_t* pa = s_aF + ls*256 + lane;
        const uint32_t* pb = s_bF + ls*256 + lane;
        uint32_t aw[2][4], bw[4][2];
        #pragma unroll
        for (int mt = 0; mt < 2; mt++)
            #pragma unroll
            for (int r = 0; r < 4; r++)
                aw[mt][r] = pa[(mt*4 + r)*32];
        #pragma unroll
        for (int wt = 0; wt < 4; wt++)
            #pragma unroll
            for (int r = 0; r < 2; r++)
                bw[wt][r] = pb[(wt*2 + r)*32];
        #pragma unroll
        for (int mt = 0; mt < 2; mt++)
            #pragma unroll
            for (int wt = 0; wt < 4; wt++)
                mma_bf16(acc[mt][wt], aw[mt][0], aw[mt][1], aw[mt][2], aw[mt][3],
                         bw[wt][0], bw[wt][1]);
    }
    __syncthreads();

    float* s_red = reinterpret_cast<float*>(s_fr);
    float* my = s_red + wid*1024;
    #pragma unroll
    for (int mt = 0; mt < 2; mt++)
        #pragma unroll
        for (int wt = 0; wt < 4; wt++)
            #pragma unroll
            for (int r = 0; r < 4; r++)
                my[((mt*4 + wt)*4 + r)*32 + lane] = acc[mt][wt][r];
    __syncthreads();

    #pragma unroll
    for (int rep = 0; rep < 4; rep++) {
        int pos = tid + rep*256;
        float v = 0.f;
        #pragma unroll
        for (int w8 = 0; w8 < 8; w8++)
            v += s_red[w8*1024 + pos];
        int lp  = pos & 31;
        int reg = (pos >> 5) & 3;
        int wt  = (pos >> 7) & 3;
        int mt  = pos >> 9;
        int grp = lp >> 2, tcp = lp & 3;
        int vv = mt*16 + grp + (reg >> 1)*8;
        int ww = wt*8 + 2*tcp + (reg & 1);
        if (vv < VV && ww < VV)
            g_Mpart[((size_t)chunk*NN*SS + (size_t)n*SS + s)*(VV*VV)
                    + vv*VV + ww] = v;
    }
}

// ---------------------------------------------------------------------------
// kA2: reduce partials, A_adp in kB's mma fragment layout, word-PAIRS adjacent:
//   g_Afrag[n][r48][lane][reg],  r48 = (s*4+kt)*4+wt
//   v = kt*8 + (lane&3) + reg*4,  w = wt*8 + (lane>>2)
// ---------------------------------------------------------------------------
__global__ void kA2(const float* __restrict__ A, const float* __restrict__ alpha)
{
    int idx = blockIdx.x * 256 + threadIdx.x;
    if (idx >= NN*48*32*2) return;
    int reg  = idx & 1;
    int lane = (idx >> 1) & 31;
    int r    = (idx >> 6) % 48;
    int n    = idx / (48*32*2);
    int wt  = r & 3;
    int kt  = (r >> 2) & 3;
    int s   = r >> 4;
    int v = kt*8 + (lane & 3) + reg*4;
    int w = wt*8 + (lane >> 2);
    float val = 0.f;
    if (v < VV && w < VV) {
        int mi = (n*SS + s)*(VV*VV) + v*VV + w;
        float m = 0.f;
        #pragma unroll
        for (int ch = 0; ch < MCH; ch++)
            m += g_Mpart[ch*(NN*SS*VV*VV) + mi];
        val = A[s*(VV*VV) + v*VV + w]
            + tanhf(m * (1.f/(float)(ICn*TD))) * alpha[0];
    }
    g_Afrag[idx] = __uint_as_float(f2tf32(val));
}

// ---------------------------------------------------------------------------
// kW: W -> [s][o][c] (native layout), BN scale folded, tf32-rounded. g_off.
// ---------------------------------------------------------------------------
__global__ void kW(const float* __restrict__ wd, const float* __restrict__ db,
                   const float* __restrict__ bng, const float* __restrict__ bnb,
                   const float* __restrict__ bnm, const float* __restrict__ bnv)
{
    int idx = blockIdx.x * 256 + threadIdx.x;
    if (idx < SS*OCn*CC) {
        int o = (idx >> 6) & 63;
        float sc = bng[o] * rsqrtf(bnv[o] + EPSF);
        g_wdT[idx] = __uint_as_float(f2tf32(wd[idx] * sc));
    }
    if (blockIdx.x == 0 && threadIdx.x < OCn) {
        int o = threadIdx.x;
        float sc = bng[o] * rsqrtf(bnv[o] + EPSF);
        float ds = db[o] + db[OCn + o] + db[2*OCn + o];
        g_off[o] = (ds - bnm[o]) * sc + bnb[o];
    }
}

// ---------------------------------------------------------------------------
// kB: block = (64-col tile, n), 4 blocks/SM. For each s:
//   GEMM1 (mma tf32): xm[col][c]; x frags reg-resident; A_adp frag pairs
//                     fetched as single LDS.64 (R14 loop order)
//   GEMM2 (mma tf32): D[col][o] += xm @ W_s; fragments via ldmatrix.x4
// Epilogue: scattered per-fragment stores + residual (R14 form).
// ---------------------------------------------------------------------------
__global__ __launch_bounds__(256, 4) void kB(
    const float* __restrict__ x,
    float* __restrict__ out)
{
    extern __shared__ float sm[];
    float* s_xm  = sm;                  // [64][68]  tf32 bits
    float* s_w   = s_xm + CT*XMS;       // [64][68]  tf32 bits, [o][k] per s
    float* s_Af  = s_w  + OCn*WST;      // [48][32][2] A_adp frag pairs, tf32
    float* s_off = s_Af + 48*32*2;      // [64]

    const int tid  = threadIdx.x;
    const int wid  = tid >> 5;
    const int lane = tid & 31;
    const int gr   = lane >> 2;
    const int tc   = lane & 3;
    const int blk  = blockIdx.x;
    const int n    = blockIdx.y;
    const int cbase = blk * CT;
    const int t0    = cbase / VV;
    const int coff  = cbase - t0*VV;

    const float* xn = x + (size_t)n*(CC*NCOL);

    // ---- prologue staging ----
    {
        const float4* ag = reinterpret_cast<const float4*>(
            g_Afrag + (size_t)n*(48*32*2));
        float4* as = reinterpret_cast<float4*>(s_Af);
        for (int idx = tid; idx < 48*32*2/4; idx += 256)
            as[idx] = ag[idx];
    }
    if (tid < OCn) s_off[tid] = g_off[tid];

    // warp roles
    const int tl = wid & 3;
    const int oh = wid >> 2;
    const int ctq = wid & 3;

    // x A-fragments in registers (s-invariant)
    uint32_t ax[2][4][4];
    {
        const int colB = (t0 + tl)*VV;
        #pragma unroll
        for (int mi = 0; mi < 2; mi++) {
            const int r0 = (oh + 2*mi)*16 + gr;
            const float* b0p = xn + (size_t)r0*NCOL;
            const float* b1p = b0p + (size_t)8*NCOL;
            #pragma unroll
            for (int kt = 0; kt < 4; kt++) {
                int c0i = colB + kt*8 + tc;
                int c1i = c0i + 4;
                bool k0 = (c0i < NCOL);
                bool k1 = (c1i < NCOL);
                ax[mi][kt][0] = f2tf32(k0 ? b0p[c0i] : 0.f);
                ax[mi][kt][1] = f2tf32(k0 ? b1p[c0i] : 0.f);
                ax[mi][kt][2] = f2tf32(k1 ? b0p[c1i] : 0.f);
                ax[mi][kt][3] = f2tf32(k1 ? b1p[c1i] : 0.f);
            }
        }
    }
    __syncthreads();   // s_Af ready

    const u64* afu2 = reinterpret_cast<const u64*>(s_Af);
    uint32_t* xmw = reinterpret_cast<uint32_t*>(s_xm);

    // ldmatrix base addresses (bytes)
    const uint32_t xm_sa = (uint32_t)__cvta_generic_to_shared(s_xm);
    const uint32_t w_sa  = (uint32_t)__cvta_generic_to_shared(s_w);
    const uint32_t addrA = xm_sa
        + (((ctq*16 + (lane & 15))*XMS + ((lane >> 4) << 2)) << 2);
    const uint32_t addrB = w_sa
        + (((oh*32 + ((lane >> 4) << 3) + (lane & 7))*WST
            + (((lane >> 3) & 1) << 2)) << 2);

    float dY[4][4];
    #pragma unroll
    for (int nt = 0; nt < 4; nt++)
        #pragma unroll
        for (int j = 0; j < 4; j++) dY[nt][j] = 0.f;

    for (int s = 0; s < SS; s++) {
        if (s) __syncthreads();
        // stage W_s: [o][k], float4 coalesced
        {
            const float4* wg = reinterpret_cast<const float4*>(
                g_wdT + s*(OCn*CC));
            for (int idx = tid; idx < OCn*CC/4; idx += 256) {
                int o = idx >> 4, c4 = (idx & 15) << 2;
                *reinterpret_cast<float4*>(&s_w[o*WST + c4]) = wg[idx];
            }
        }

        // ---- GEMM1 via mma (R14 order): frag pairs via LDS.64 ----
        #pragma unroll
        for (int mi = 0; mi < 2; mi++) {
            const int c0 = (oh + 2*mi)*16;
            #pragma unroll
            for (int wt = 0; wt < 4; wt++) {
                float d[4] = {0.f, 0.f, 0.f, 0.f};
                #pragma unroll
                for (int kt = 0; kt < 4; kt++) {
                    u64 bw = afu2[((s*4 + kt)*4 + wt)*32 + lane];
                    mma_tf32(d, ax[mi][kt][0], ax[mi][kt][1],
                                ax[mi][kt][2], ax[mi][kt][3],
                                (uint32_t)bw, (uint32_t)(bw >> 32));
                }
                int w0  = wt*8 + 2*tc;
                int lc0 = tl*VV + w0 - coff;
                if (w0 < VV && lc0 >= 0 && lc0 < CT) {
                    xmw[lc0*XMS + c0 + gr]     = f2tf32(d[0]);
                    xmw[lc0*XMS + c0 + gr + 8] = f2tf32(d[2]);
                }
                int w1  = w0 + 1;
                int lc1 = lc0 + 1;
                if (w1 < VV && lc1 >= 0 && lc1 < CT) {
                    xmw[lc1*XMS + c0 + gr]     = f2tf32(d[1]);
                    xmw[lc1*XMS + c0 + gr + 8] = f2tf32(d[3]);
                }
            }
        }
        __syncthreads();

        // ---- GEMM2 via mma: K = 64 (this s); frags via ldmatrix ----
        #pragma unroll 2
        for (int kq = 0; kq < 8; kq++) {
            const uint32_t koff = (uint32_t)(kq*8) << 2;
            uint32_t a[4], b01[4], b23[4];
            ldsm4(a,   addrA + koff);
            ldsm4(b01, addrB + koff);
            ldsm4(b23, addrB + (16*WST << 2) + koff);
            mma_tf32(dY[0], a[0], a[1], a[2], a[3], b01[0], b01[1]);
            mma_tf32(dY[1], a[0], a[1], a[2], a[3], b01[2], b01[3]);
            mma_tf32(dY[2], a[0], a[1], a[2], a[3], b23[0], b23[1]);
            mma_tf32(dY[3], a[0], a[1], a[2], a[3], b23[2], b23[3]);
        }
    }

    // ---- epilogue (R14 scattered form) ----
    {
        const int row0 = ctq*16 + gr;
        const int row1 = row0 + 8;
        const int colg0 = cbase + row0;
        const int colg1 = cbase + row1;
        const bool ok0 = (colg0 < NCOL);
        const bool ok1 = (colg1 < NCOL);
        float* on = out + (size_t)n*(CC*NCOL);
        #pragma unroll
        for (int nt = 0; nt < 4; nt++) {
            int oe = oh*32 + nt*8 + 2*tc;
            int oo = oe + 1;
            float offe = s_off[oe], offo = s_off[oo];
            if (ok0) {
                float v0 = dY[nt][0] + offe + xn[(size_t)oe*NCOL + colg0];
                float v1 = dY[nt][1] + offo + xn[(size_t)oo*NCOL + colg0];
                on[(size_t)oe*NCOL + colg0] = fmaxf(v0, 0.f);
                on[(size_t)oo*NCOL + colg0] = fmaxf(v1, 0.f);
            }
            if (ok1) {
                float v2 = dY[nt][2] + offe + xn[(size_t)oe*NCOL + colg1];
                float v3 = dY[nt][3] + offo + xn[(size_t)oo*NCOL + colg1];
                on[(size_t)oe*NCOL + colg1] = fmaxf(v2, 0.f);
                on[(size_t)oo*NCOL + colg1] = fmaxf(v3, 0.f);
            }
        }
    }
}

// ---------------------------------------------------------------------------
extern "C" void kernel_launch(void* const* d_in, const int* in_sizes, int n_in,
                              void* d_out, int out_size)
{
    const float* x     = (const float*)d_in[0];
    const float* A     = (const float*)d_in[1];
    const float* alpha = (const float*)d_in[2];
    const float* caw   = (const float*)d_in[3];
    const float* cab   = (const float*)d_in[4];
    const float* cbw   = (const float*)d_in[5];
    const float* cbb   = (const float*)d_in[6];
    const float* bag   = (const float*)d_in[7];
    const float* babt  = (const float*)d_in[8];
    const float* bam   = (const float*)d_in[9];
    const float* bav   = (const float*)d_in[10];
    const float* bbg   = (const float*)d_in[11];
    const float* bbbt  = (const float*)d_in[12];
    const float* bbm   = (const float*)d_in[13];
    const float* bbv   = (const float*)d_in[14];
    const float* cdw   = (const float*)d_in[15];
    const float* cdb   = (const float*)d_in[16];
    const float* bng   = (const float*)d_in[17];
    const float* bnb   = (const float*)d_in[18];
    const float* bnm   = (const float*)d_in[19];
    const float* bnv   = (const float*)d_in[20];
    float* out = (float*)d_out;

    const int smemB = (CT*XMS + OCn*WST + 48*32*2 + 64) * sizeof(float);
    cudaFuncSetAttribute(kB, cudaFuncAttributeMaxDynamicSharedMemorySize, smemB);

    // 4 launches: kB is the 4th (ncu capture slot)
    kW<<<(SS*OCn*CC + 255)/256, 256>>>(cdw, cdb, bng, bnb, bnm, bnv);
    kConvM<<<dim3(MCH, SS, NN), 256>>>(x, caw, cab, cbw, cbb,
                                       bag, babt, bam, bav,
                                       bbg, bbbt, bbm, bbv);
    kA2<<<(NN*48*32*2 + 255)/256, 256>>>(A, alpha);
    kB<<<dim3(NTBL, NN), 256, smemB>>>(x, out);
}